// round 17
// baseline (speedup 1.0000x reference)
#include <cuda_runtime.h>
#include <cuda_fp16.h>
#include <cstdint>

#define MMV 2048
#define NNV 4096
#define KKV 4096

// Scratch (__device__ globals; no allocations allowed)
__device__ __align__(16) __half g_xh[(size_t)MMV * KKV];  // fp16(x)
__device__ __align__(16) __half g_wd[(size_t)KKV * NNV];  // fp16(s*(q-z)), [K][N]

// ---------------------------------------------------------------------------
// asm helpers
// ---------------------------------------------------------------------------
__device__ __forceinline__ void ldsm4(uint32_t* r, uint32_t addr) {
    asm volatile("ldmatrix.sync.aligned.m8n8.x4.shared.b16 {%0,%1,%2,%3}, [%4];"
                 : "=r"(r[0]), "=r"(r[1]), "=r"(r[2]), "=r"(r[3]) : "r"(addr));
}
__device__ __forceinline__ void ldsm4t(uint32_t* r, uint32_t addr) {
    asm volatile("ldmatrix.sync.aligned.m8n8.x4.trans.shared.b16 {%0,%1,%2,%3}, [%4];"
                 : "=r"(r[0]), "=r"(r[1]), "=r"(r[2]), "=r"(r[3]) : "r"(addr));
}
__device__ __forceinline__ void mma_f16(float* c, const uint32_t* a, const uint32_t* b) {
    asm volatile("mma.sync.aligned.m16n8k16.row.col.f32.f16.f16.f32 "
                 "{%0,%1,%2,%3}, {%4,%5,%6,%7}, {%8,%9}, {%0,%1,%2,%3};"
                 : "+f"(c[0]), "+f"(c[1]), "+f"(c[2]), "+f"(c[3])
                 : "r"(a[0]), "r"(a[1]), "r"(a[2]), "r"(a[3]), "r"(b[0]), "r"(b[1]));
}
__device__ __forceinline__ void cpa16(uint32_t s, const void* g) {
    asm volatile("cp.async.cg.shared.global [%0], [%1], 16;" :: "r"(s), "l"(g));
}
#define CP_COMMIT() asm volatile("cp.async.commit_group;" ::: "memory")
#define CP_WAIT0()  asm volatile("cp.async.wait_group 0;" ::: "memory")

// ---------------------------------------------------------------------------
// Fused prep (unchanged from R15):
//   blocks [0,4096):     x -> fp16, 8 floats in (2x float4), one uint4 out
//   blocks [4096,5120):  W unpack, 8 n per thread -> 8x uint4 coalesced stores
// ---------------------------------------------------------------------------
__global__ void prep_kernel(const float4* __restrict__ x4,
                            const int* __restrict__ qw,
                            const float* __restrict__ zp,
                            const float* __restrict__ scales)
{
    if (blockIdx.x < 4096) {
        size_t i = (size_t)blockIdx.x * blockDim.x + threadIdx.x;   // over M*K/8
        float4 a = x4[2 * i], b = x4[2 * i + 1];
        __half2 h0 = __floats2half2_rn(a.x, a.y);
        __half2 h1 = __floats2half2_rn(a.z, a.w);
        __half2 h2 = __floats2half2_rn(b.x, b.y);
        __half2 h3 = __floats2half2_rn(b.z, b.w);
        uint4 o;
        o.x = *(uint32_t*)&h0; o.y = *(uint32_t*)&h1;
        o.z = *(uint32_t*)&h2; o.w = *(uint32_t*)&h3;
        ((uint4*)g_xh)[i] = o;
    } else {
        int T = (int)((blockIdx.x - 4096) * blockDim.x + threadIdx.x); // < 512*512
        int ng = T & 511;           // n-group (8 n's)
        int kp = T >> 9;            // packed row 0..511
        int g  = kp >> 4;
        int n0 = ng * 8;

        const float4* zp4 = (const float4*)(zp     + (size_t)g * NNV + n0);
        const float4* sc4 = (const float4*)(scales + (size_t)g * NNV + n0);
        float4 za = zp4[0], zb = zp4[1];
        float4 sa = sc4[0], sb = sc4[1];
        float zv[8] = {za.x, za.y, za.z, za.w, zb.x, zb.y, zb.z, zb.w};
        float sv[8] = {sa.x, sa.y, sa.z, sa.w, sb.x, sb.y, sb.z, sb.w};
#pragma unroll
        for (int i = 0; i < 8; ++i) {
            zv[i] = fminf(fmaxf(rintf(zv[i]), 0.0f), 15.0f);
            sv[i] = fminf(fmaxf(sv[i], 1e-5f), 1e4f);
        }
        int q[8];
#pragma unroll
        for (int i = 0; i < 8; ++i)
            q[i] = qw[(size_t)kp * NNV + n0 + i];

#pragma unroll
        for (int j = 0; j < 8; ++j) {
            __align__(16) __half h[8];
#pragma unroll
            for (int i = 0; i < 8; ++i) {
                float w = (float)((q[i] >> (4 * j)) & 15);
                h[i] = __float2half_rn((w - zv[i]) * sv[i]);
            }
            *(uint4*)(g_wd + (size_t)(kp * 8 + j) * NNV + n0) = *(uint4*)h;
        }
    }
}

// ---------------------------------------------------------------------------
// GEMM: C = xh @ Wd + bias.
// CTA tile 64x128, BK=64, 4 warps (2m x 2n), warp tile 32x64 — R9 compute
// body. NS=2 double buffer (48 KB smem) + 128-reg cap -> 4 CTAs/SM.
// Iteration order (race-free): wait_group 0 -> syncthreads -> issue kt+1 ->
// compute kt. Prefetch distance = one full iteration.
// ---------------------------------------------------------------------------
#define NS 2
#define STG_BYTES 24576
#define SMEM_TOTAL (NS * STG_BYTES)   // 49152

__global__ void __launch_bounds__(128, 4)
gemm_kernel(const float* __restrict__ bias,
            float* __restrict__ C)
{
    extern __shared__ __align__(16) char smem[];
    const uint32_t sb = (uint32_t)__cvta_generic_to_shared(smem);
    const int tid = threadIdx.x, lane = tid & 31, wid = tid >> 5;
    const int wm = wid & 1, wn = wid >> 1;
    const int m0 = blockIdx.y * 64, n0 = blockIdx.x * 128;

    // loader: A 64x64 fp16 (512 x 16B chunks), B 64x128 fp16 (1024 chunks)
    auto load_stage = [&](int kt, int st) {
        uint32_t base = sb + st * STG_BYTES;
#pragma unroll
        for (int j = 0; j < 4; ++j) {
            int q = tid + j * 128;
            int r = q >> 3, c = q & 7;
            uint32_t so = base + (uint32_t)(r * 8 + (c ^ (r & 7))) * 16;
            cpa16(so, g_xh + (size_t)(m0 + r) * KKV + kt * 64 + c * 8);
        }
#pragma unroll
        for (int j = 0; j < 8; ++j) {
            int q = tid + j * 128;
            int r = q >> 4, c = q & 15;
            uint32_t so = base + 8192 + (uint32_t)(r * 16 + (c ^ (r & 7))) * 16;
            cpa16(so, g_wd + (size_t)(kt * 64 + r) * NNV + n0 + c * 8);
        }
    };

    // prefill stage 0
    load_stage(0, 0); CP_COMMIT();

    // ldmatrix address precompute
    const int lane_r = lane & 15, chh = lane >> 4;
    uint32_t arow[2], axr[2];
#pragma unroll
    for (int t = 0; t < 2; ++t) {
        int r = wm * 32 + t * 16 + lane_r;
        arow[t] = (uint32_t)r * 128;            // 128 B per A row
        axr[t]  = (uint32_t)(r & 7);
    }
    const uint32_t xb = (uint32_t)(lane_r & 7);
    uint32_t bcol[4];
#pragma unroll
    for (int bb = 0; bb < 4; ++bb)
        bcol[bb] = (uint32_t)(wn * 8 + (((uint32_t)(bb * 2 + chh)) ^ xb)) * 16;
    uint32_t boff[4];
#pragma unroll
    for (int ks = 0; ks < 4; ++ks)
        boff[ks] = (uint32_t)(ks * 16 + lane_r) * 256;   // 256 B per B row

    float accM[2][8][4];
#pragma unroll
    for (int t = 0; t < 2; ++t)
#pragma unroll
        for (int nt = 0; nt < 8; ++nt)
#pragma unroll
            for (int i = 0; i < 4; ++i) accM[t][nt][i] = 0.f;

    for (int kt = 0; kt < 64; ++kt) {
        CP_WAIT0();        // my loads for stage kt complete
        __syncthreads();   // => everyone's complete => stage kt fully visible,
                           //    and all reads of slot (kt+1)&1 (iter kt-1) retired
        if (kt + 1 < 64) { load_stage(kt + 1, (kt + 1) & 1); CP_COMMIT(); }

        const uint32_t Ab = sb + (kt & 1) * STG_BYTES;
        const uint32_t Bb = Ab + 8192;

#pragma unroll
        for (int ks = 0; ks < 4; ++ks) {
            uint32_t af[2][4], bfr[4][4];
#pragma unroll
            for (int t = 0; t < 2; ++t) {
                uint32_t co = ((uint32_t)(ks * 2 + chh) ^ axr[t]) * 16;
                ldsm4(af[t], Ab + arow[t] + co);
            }
#pragma unroll
            for (int bb = 0; bb < 4; ++bb)
                ldsm4t(bfr[bb], Bb + boff[ks] + bcol[bb]);
#pragma unroll
            for (int t = 0; t < 2; ++t)
#pragma unroll
                for (int nt = 0; nt < 8; ++nt)
                    mma_f16(accM[t][nt], af[t], &bfr[nt >> 1][(nt & 1) * 2]);
        }
    }

    // epilogue
#pragma unroll
    for (int t = 0; t < 2; ++t) {
        int row0 = m0 + wm * 32 + t * 16 + (lane >> 2);
#pragma unroll
        for (int nt = 0; nt < 8; ++nt) {
            int col = n0 + wn * 64 + nt * 8 + (lane & 3) * 2;
            float2 b = *(const float2*)(bias + col);
            float2 o0, o1;
            o0.x = accM[t][nt][0] + b.x;  o0.y = accM[t][nt][1] + b.y;
            o1.x = accM[t][nt][2] + b.x;  o1.y = accM[t][nt][3] + b.y;
            *(float2*)(C + (size_t)row0 * NNV + col)       = o0;
            *(float2*)(C + (size_t)(row0 + 8) * NNV + col) = o1;
        }
    }
}

// ---------------------------------------------------------------------------
// Host. Inputs: x, scales, zero_points, bias, qweight
// ---------------------------------------------------------------------------
extern "C" void kernel_launch(void* const* d_in, const int* in_sizes, int n_in,
                              void* d_out, int out_size)
{
    const float* x      = (const float*)d_in[0];
    const float* scales = (const float*)d_in[1];
    const float* zp     = (const float*)d_in[2];
    const float* bias   = (const float*)d_in[3];
    const int*   qw     = (const int*)d_in[4];
    float*       out    = (float*)d_out;

    prep_kernel<<<5120, 256>>>((const float4*)x, qw, zp, scales);

    static bool attr_set = false;
    if (!attr_set) {
        cudaFuncSetAttribute(gemm_kernel, cudaFuncAttributeMaxDynamicSharedMemorySize, SMEM_TOTAL);
        attr_set = true;
    }
    gemm_kernel<<<dim3(NNV / 128, MMV / 64), 128, SMEM_TOTAL>>>(bias, out);
}